// round 2
// baseline (speedup 1.0000x reference)
#include <cuda_runtime.h>
#include <math_constants.h>

#define BB 2
#define SS 2048
#define DD 1024
#define HH 16
#define DHD 64
#define MTOT (BB*SS)   // 4096
#define COUT 512

// ---------------- scratch (device globals; no allocation allowed) -------------
__device__ float g_q [BB*HH*SS*DHD];   // [B,H,S,DH]
__device__ float g_km[BB*HH*SS*DHD];   // merged K: (1-g)*kh + g*(conv+bias)
__device__ float g_v [BB*HH*SS*DHD];
__device__ float g_ao[BB*SS*DD];       // attention out, [B,S,D]
__device__ float g_wt0[3*COUT*DD];     // conv w0 transposed: [t][co][ci]
__device__ float g_wt1[5*COUT*DD];

__device__ __forceinline__ float sigm(float x){ return 1.0f/(1.0f+__expf(-x)); }

// ---------------- weight transpose for conv (t-major) ------------------------
__global__ void prep_wt(const float* __restrict__ w0, const float* __restrict__ w1){
    int idx = blockIdx.x*blockDim.x + threadIdx.x;
    const int tot0 = 3*COUT*DD;
    const int tot1 = 5*COUT*DD;
    if (idx < tot0){
        int t = idx/(COUT*DD); int r = idx%(COUT*DD);
        int co = r/DD, ci = r%DD;
        g_wt0[idx] = w0[(co*DD+ci)*3 + t];
    }
    if (idx < tot1){
        int t = idx/(COUT*DD); int r = idx%(COUT*DD);
        int co = r/DD, ci = r%DD;
        g_wt1[idx] = w1[(co*DD+ci)*5 + t];
    }
}

// ---------------- 128x128x16 NT GEMM: Y = X @ W^T ----------------------------
// MODE 0: dst = g_q (head layout)
// MODE 1: dst = g_km, scaled by (1 - sigmoid(gate[h]))
// MODE 3: dst = g_v (head layout)
// MODE 2: dst = out param, plain [m,n] + bias; X = g_ao
#define LDA 132
template<int MODE>
__global__ __launch_bounds__(256) void gemm_nt(const float* __restrict__ X,
                                               const float* __restrict__ W,
                                               float* __restrict__ dstp,
                                               const float* __restrict__ aux){
    __shared__ float As[16][LDA];
    __shared__ float Bs[16][LDA];
    const int m0 = blockIdx.y*128, n0 = blockIdx.x*128;
    const int tid = threadIdx.x;
    const int tx = tid & 15, ty = tid >> 4;
    const int lr = tid >> 2, lc = (tid & 3)*4;

    const float* Xp = (MODE==2) ? g_ao : X;

    float acc[8][8];
    #pragma unroll
    for (int i=0;i<8;i++)
        #pragma unroll
        for (int j=0;j<8;j++) acc[i][j]=0.0f;

    for (int k0=0; k0<DD; k0+=16){
        #pragma unroll
        for (int h2=0; h2<2; h2++){
            int row = m0 + lr + h2*64;
            float4 a = *(const float4*)&Xp[row*DD + k0 + lc];
            As[lc+0][lr+h2*64]=a.x; As[lc+1][lr+h2*64]=a.y;
            As[lc+2][lr+h2*64]=a.z; As[lc+3][lr+h2*64]=a.w;
            int rowb = n0 + lr + h2*64;
            float4 b = *(const float4*)&W[rowb*DD + k0 + lc];
            Bs[lc+0][lr+h2*64]=b.x; Bs[lc+1][lr+h2*64]=b.y;
            Bs[lc+2][lr+h2*64]=b.z; Bs[lc+3][lr+h2*64]=b.w;
        }
        __syncthreads();
        #pragma unroll
        for (int kk=0; kk<16; kk++){
            float4 a0 = *(const float4*)&As[kk][ty*4];
            float4 a1 = *(const float4*)&As[kk][64+ty*4];
            float4 b0 = *(const float4*)&Bs[kk][tx*4];
            float4 b1 = *(const float4*)&Bs[kk][64+tx*4];
            float ar[8] = {a0.x,a0.y,a0.z,a0.w,a1.x,a1.y,a1.z,a1.w};
            float br[8] = {b0.x,b0.y,b0.z,b0.w,b1.x,b1.y,b1.z,b1.w};
            #pragma unroll
            for (int i=0;i<8;i++)
                #pragma unroll
                for (int j=0;j<8;j++) acc[i][j] = fmaf(ar[i], br[j], acc[i][j]);
        }
        __syncthreads();
    }

    float* dst = (MODE==0) ? g_q : (MODE==1) ? g_km : (MODE==3) ? g_v : dstp;

    #pragma unroll
    for (int i=0;i<8;i++){
        int m = m0 + ((i<4) ? (ty*4+i) : (64+ty*4+i-4));
        int bidx = m >> 11;           // /S
        int s    = m & (SS-1);
        #pragma unroll
        for (int jg=0; jg<2; jg++){
            int n = n0 + ((jg==0) ? tx*4 : 64+tx*4);
            float4 v;
            v.x = acc[i][jg*4+0]; v.y = acc[i][jg*4+1];
            v.z = acc[i][jg*4+2]; v.w = acc[i][jg*4+3];
            if (MODE==2){
                v.x += aux[n+0]; v.y += aux[n+1]; v.z += aux[n+2]; v.w += aux[n+3];
                *(float4*)&dst[m*DD + n] = v;
            } else {
                int h = n >> 6, d = n & 63;
                if (MODE==1){
                    float gsc = 1.0f - sigm(aux[h]);
                    v.x*=gsc; v.y*=gsc; v.z*=gsc; v.w*=gsc;
                }
                *(float4*)&dst[((bidx*HH+h)*SS + s)*DHD + d] = v;
            }
        }
    }
}

// ---------------- conv-as-GEMM, accumulates g*conv into g_km ------------------
__global__ __launch_bounds__(256) void conv_gemm(const float* __restrict__ kin,
                                                 const float* __restrict__ cb0,
                                                 const float* __restrict__ cb1,
                                                 const float* __restrict__ gate){
    __shared__ float As[16][LDA];
    __shared__ float Bs[16][LDA];
    const int branch = blockIdx.x >> 2;
    const int n0 = (blockIdx.x & 3)*128;
    const int m0 = blockIdx.y*128;
    const float* wt   = branch ? g_wt1 : g_wt0;
    const float* bias = branch ? cb1 : cb0;
    const int ksz = branch ? 5 : 3;
    const int pad = ksz >> 1;
    const int Kp  = ksz << 10;

    const int tid = threadIdx.x;
    const int tx = tid & 15, ty = tid >> 4;
    const int lr = tid >> 2, lc = (tid & 3)*4;

    float acc[8][8];
    #pragma unroll
    for (int i=0;i<8;i++)
        #pragma unroll
        for (int j=0;j<8;j++) acc[i][j]=0.0f;

    for (int k0=0; k0<Kp; k0+=16){
        int t   = k0 >> 10;        // constant across 16-wide tile (16 | 1024)
        int ci0 = k0 & 1023;
        int shift = t - pad;
        #pragma unroll
        for (int h2=0; h2<2; h2++){
            int m = m0 + lr + h2*64;
            int bidx = m >> 11;
            int s = (m & (SS-1)) + shift;
            float4 a = make_float4(0.f,0.f,0.f,0.f);
            if (s >= 0 && s < SS)
                a = *(const float4*)&kin[(bidx*SS + s)*DD + ci0 + lc];
            As[lc+0][lr+h2*64]=a.x; As[lc+1][lr+h2*64]=a.y;
            As[lc+2][lr+h2*64]=a.z; As[lc+3][lr+h2*64]=a.w;
            int co = n0 + lr + h2*64;
            float4 b = *(const float4*)&wt[(t*COUT+co)*DD + ci0 + lc];
            Bs[lc+0][lr+h2*64]=b.x; Bs[lc+1][lr+h2*64]=b.y;
            Bs[lc+2][lr+h2*64]=b.z; Bs[lc+3][lr+h2*64]=b.w;
        }
        __syncthreads();
        #pragma unroll
        for (int kk=0; kk<16; kk++){
            float4 a0 = *(const float4*)&As[kk][ty*4];
            float4 a1 = *(const float4*)&As[kk][64+ty*4];
            float4 b0 = *(const float4*)&Bs[kk][tx*4];
            float4 b1 = *(const float4*)&Bs[kk][64+tx*4];
            float ar[8] = {a0.x,a0.y,a0.z,a0.w,a1.x,a1.y,a1.z,a1.w};
            float br[8] = {b0.x,b0.y,b0.z,b0.w,b1.x,b1.y,b1.z,b1.w};
            #pragma unroll
            for (int i=0;i<8;i++)
                #pragma unroll
                for (int j=0;j<8;j++) acc[i][j] = fmaf(ar[i], br[j], acc[i][j]);
        }
        __syncthreads();
    }

    #pragma unroll
    for (int i=0;i<8;i++){
        int m = m0 + ((i<4) ? (ty*4+i) : (64+ty*4+i-4));
        int bidx = m >> 11;
        int s    = m & (SS-1);
        #pragma unroll
        for (int jg=0; jg<2; jg++){
            int co = n0 + ((jg==0) ? tx*4 : 64+tx*4);
            int gc = branch*COUT + co;
            int h = gc >> 6, d = gc & 63;
            float g = sigm(gate[h]);
            float4* p = (float4*)&g_km[((bidx*HH+h)*SS + s)*DHD + d];
            float4 old = *p;
            old.x += g*(acc[i][jg*4+0] + bias[co+0]);
            old.y += g*(acc[i][jg*4+1] + bias[co+1]);
            old.z += g*(acc[i][jg*4+2] + bias[co+2]);
            old.w += g*(acc[i][jg*4+3] + bias[co+3]);
            *p = old;
        }
    }
}

// ---------------- flash attention (64-row q tiles, online softmax) ------------
#define LDP 68
__global__ __launch_bounds__(256) void flash_attn(const int* __restrict__ mask){
    extern __shared__ float sm[];
    float (*Qs)[LDP] = (float(*)[LDP])(sm);              // [d][m]
    float (*Ks)[LDP] = (float(*)[LDP])(sm +   64*LDP);   // [d][n]
    float (*Vs)[LDP] = (float(*)[LDP])(sm + 2*64*LDP);   // [jk][d]
    float (*Ps)[LDP] = (float(*)[LDP])(sm + 3*64*LDP);   // [jk][m]

    const int bh = blockIdx.y;
    const int bidx = bh >> 4, h = bh & 15;
    const int q0 = blockIdx.x*64;
    const int tid = threadIdx.x;
    const int tx = tid & 15, ty = tid >> 4;
    const int lr = tid >> 2, lc4 = tid & 3;

    const float* Qg = g_q  + (size_t)bh*SS*DHD;
    const float* Kg = g_km + (size_t)bh*SS*DHD;
    const float* Vg = g_v  + (size_t)bh*SS*DHD;

    #pragma unroll
    for (int jj=0; jj<4; jj++){
        int c = (lc4 + jj*4)*4;
        float4 qv = *(const float4*)&Qg[(q0+lr)*DHD + c];
        Qs[c+0][lr]=qv.x; Qs[c+1][lr]=qv.y; Qs[c+2][lr]=qv.z; Qs[c+3][lr]=qv.w;
    }

    float m_run[4] = {-CUDART_INF_F,-CUDART_INF_F,-CUDART_INF_F,-CUDART_INF_F};
    float l_run[4] = {0.f,0.f,0.f,0.f};
    float o[4][4];
    #pragma unroll
    for (int i=0;i<4;i++)
        #pragma unroll
        for (int j=0;j<4;j++) o[i][j]=0.f;

    const float scl = 0.125f;   // 1/sqrt(64)
    const float NEG = -1e9f;

    for (int kb=0; kb<SS/64; kb++){
        int k0 = kb*64;
        #pragma unroll
        for (int jj=0; jj<4; jj++){
            int c = (lc4 + jj*4)*4;
            float4 kv = *(const float4*)&Kg[(k0+lr)*DHD + c];
            Ks[c+0][lr]=kv.x; Ks[c+1][lr]=kv.y; Ks[c+2][lr]=kv.z; Ks[c+3][lr]=kv.w;
            float4 vv = *(const float4*)&Vg[(k0+lr)*DHD + c];
            *(float4*)&Vs[lr][c] = vv;
        }
        __syncthreads();

        float sc[4][4];
        #pragma unroll
        for (int i=0;i<4;i++)
            #pragma unroll
            for (int j=0;j<4;j++) sc[i][j]=0.f;

        #pragma unroll 16
        for (int kt=0; kt<64; kt++){
            float4 aq = *(const float4*)&Qs[kt][ty*4];
            float4 bk = *(const float4*)&Ks[kt][tx*4];
            float ar[4]={aq.x,aq.y,aq.z,aq.w};
            float br[4]={bk.x,bk.y,bk.z,bk.w};
            #pragma unroll
            for (int i=0;i<4;i++)
                #pragma unroll
                for (int j=0;j<4;j++) sc[i][j] = fmaf(ar[i], br[j], sc[i][j]);
        }

        // mask + scale
        #pragma unroll
        for (int i=0;i<4;i++){
            const int4 mr = *(const int4*)&mask[((size_t)bidx*SS + q0+ty*4+i)*SS + k0 + tx*4];
            sc[i][0] = mr.x ? sc[i][0]*scl : NEG;
            sc[i][1] = mr.y ? sc[i][1]*scl : NEG;
            sc[i][2] = mr.z ? sc[i][2]*scl : NEG;
            sc[i][3] = mr.w ? sc[i][3]*scl : NEG;
        }

        // online softmax (row groups: 16 threads sharing ty within a warp)
        #pragma unroll
        for (int i=0;i<4;i++){
            float rm = fmaxf(fmaxf(sc[i][0],sc[i][1]), fmaxf(sc[i][2],sc[i][3]));
            #pragma unroll
            for (int off=8; off>=1; off>>=1)
                rm = fmaxf(rm, __shfl_xor_sync(0xffffffffu, rm, off));
            float mnew = fmaxf(m_run[i], rm);
            float corr = __expf(m_run[i] - mnew);
            float ps = 0.f;
            #pragma unroll
            for (int j=0;j<4;j++){
                float p = __expf(sc[i][j] - mnew);
                Ps[tx*4+j][ty*4+i] = p;
                ps += p;
            }
            #pragma unroll
            for (int off=8; off>=1; off>>=1)
                ps += __shfl_xor_sync(0xffffffffu, ps, off);
            l_run[i] = l_run[i]*corr + ps;
            m_run[i] = mnew;
            o[i][0]*=corr; o[i][1]*=corr; o[i][2]*=corr; o[i][3]*=corr;
        }
        __syncthreads();

        #pragma unroll 16
        for (int jk=0; jk<64; jk++){
            float4 pp = *(const float4*)&Ps[jk][ty*4];
            float4 vv = *(const float4*)&Vs[jk][tx*4];
            float pr[4]={pp.x,pp.y,pp.z,pp.w};
            float vr[4]={vv.x,vv.y,vv.z,vv.w};
            #pragma unroll
            for (int i=0;i<4;i++)
                #pragma unroll
                for (int j=0;j<4;j++) o[i][j] = fmaf(pr[i], vr[j], o[i][j]);
        }
        __syncthreads();
    }

    #pragma unroll
    for (int i=0;i<4;i++){
        float inv = 1.0f / l_run[i];
        int srow = q0 + ty*4 + i;
        float4 v;
        v.x=o[i][0]*inv; v.y=o[i][1]*inv; v.z=o[i][2]*inv; v.w=o[i][3]*inv;
        *(float4*)&g_ao[((size_t)bidx*SS + srow)*DD + h*DHD + tx*4] = v;
    }
}

// ---------------- launch ------------------------------------------------------
extern "C" void kernel_launch(void* const* d_in, const int* in_sizes, int n_in,
                              void* d_out, int out_size){
    const float* q    = (const float*)d_in[0];
    const float* k    = (const float*)d_in[1];
    const float* v    = (const float*)d_in[2];
    const int*   mask = (const int*)  d_in[3];
    const float* Wq   = (const float*)d_in[4];
    const float* Wk   = (const float*)d_in[5];
    const float* Wv   = (const float*)d_in[6];
    const float* Wo   = (const float*)d_in[7];
    const float* bo   = (const float*)d_in[8];
    const float* cw0  = (const float*)d_in[9];
    const float* cb0  = (const float*)d_in[10];
    const float* cw1  = (const float*)d_in[11];
    const float* cb1  = (const float*)d_in[12];
    const float* gate = (const float*)d_in[13];
    float* out = (float*)d_out;

    dim3 blk(256);
    dim3 gproj(DD/128, MTOT/128);   // (8, 32)

    prep_wt<<<(5*COUT*DD + 255)/256, 256>>>(cw0, cw1);
    gemm_nt<0><<<gproj, blk>>>(q, Wq, nullptr, nullptr);
    gemm_nt<1><<<gproj, blk>>>(k, Wk, nullptr, gate);
    gemm_nt<3><<<gproj, blk>>>(v, Wv, nullptr, nullptr);
    conv_gemm<<<dim3(8,32), blk>>>(k, cb0, cb1, gate);

    int smem = 4*64*LDP*sizeof(float);  // ~69.6 KB
    cudaFuncSetAttribute(flash_attn, cudaFuncAttributeMaxDynamicSharedMemorySize, smem);
    flash_attn<<<dim3(SS/64, BB*HH), blk, smem>>>(mask);

    gemm_nt<2><<<gproj, blk>>>(nullptr, Wo, out, bo);
}

// round 6
// speedup vs baseline: 1.3279x; 1.3279x over previous
#include <cuda_runtime.h>
#include <cuda_bf16.h>
#include <mma.h>
#include <math_constants.h>

using namespace nvcuda;

#define BB 2
#define SS 2048
#define DD 1024
#define HH 16
#define DHD 64
#define MTOT (BB*SS)   // 4096
#define COUT 512

typedef __nv_bfloat16 bf16;

// ---------------- scratch (device globals; no allocation allowed) -------------
__device__ float g_q [BB*HH*SS*DHD];   // [B,H,S,DH]
__device__ float g_km[BB*HH*SS*DHD];   // merged K: (1-g)*kh + g*(conv+bias)
__device__ float g_v [BB*HH*SS*DHD];
__device__ float g_ao[BB*SS*DD];       // attention out, [B,S,D]

// bf16 hi/lo splits
__device__ bf16 g_qh[MTOT*DD],  g_ql[MTOT*DD];
__device__ bf16 g_kh[MTOT*DD],  g_kl[MTOT*DD];
__device__ bf16 g_vh[MTOT*DD],  g_vl[MTOT*DD];
__device__ bf16 g_aoh[MTOT*DD], g_aol[MTOT*DD];
__device__ bf16 g_Wqh[DD*DD], g_Wql[DD*DD];
__device__ bf16 g_Wkh[DD*DD], g_Wkl[DD*DD];
__device__ bf16 g_Wvh[DD*DD], g_Wvl[DD*DD];
__device__ bf16 g_Woh[DD*DD], g_Wol[DD*DD];
__device__ bf16 g_wt0h[3*COUT*DD], g_wt0l[3*COUT*DD];   // [t][co][ci]
__device__ bf16 g_wt1h[5*COUT*DD], g_wt1l[5*COUT*DD];

__device__ __forceinline__ float sigm(float x){ return 1.0f/(1.0f+__expf(-x)); }

// ---------------- fp32 -> bf16 hi/lo split ------------------------------------
// SEL: 0 q, 1 k, 2 v, 3 Wq, 4 Wk, 5 Wv, 6 Wo, 7 ao (src ignored, reads g_ao)
template<int SEL>
__global__ void cvt_hilo(const float* __restrict__ src, int n4){
    int i = blockIdx.x*blockDim.x + threadIdx.x;
    if (i >= n4) return;

    const float4* s4 = (const float4*)src;
    uint2* hi; uint2* lo;
    if (SEL==0){ hi=(uint2*)g_qh;  lo=(uint2*)g_ql;  }
    if (SEL==1){ hi=(uint2*)g_kh;  lo=(uint2*)g_kl;  }
    if (SEL==2){ hi=(uint2*)g_vh;  lo=(uint2*)g_vl;  }
    if (SEL==3){ hi=(uint2*)g_Wqh; lo=(uint2*)g_Wql; }
    if (SEL==4){ hi=(uint2*)g_Wkh; lo=(uint2*)g_Wkl; }
    if (SEL==5){ hi=(uint2*)g_Wvh; lo=(uint2*)g_Wvl; }
    if (SEL==6){ hi=(uint2*)g_Woh; lo=(uint2*)g_Wol; }
    if (SEL==7){ hi=(uint2*)g_aoh; lo=(uint2*)g_aol; s4=(const float4*)g_ao; }

    float4 f = s4[i];
    float fv[4] = {f.x, f.y, f.z, f.w};
    unsigned int hw[4], lw[4];
    #pragma unroll
    for (int j=0;j<4;j++){
        bf16 h = __float2bfloat16(fv[j]);
        bf16 l = __float2bfloat16(fv[j] - __bfloat162float(h));
        hw[j] = (unsigned int)__bfloat16_as_ushort(h);
        lw[j] = (unsigned int)__bfloat16_as_ushort(l);
    }
    hi[i] = make_uint2(hw[0] | (hw[1]<<16), hw[2] | (hw[3]<<16));
    lo[i] = make_uint2(lw[0] | (lw[1]<<16), lw[2] | (lw[3]<<16));
}

// ---------------- conv weight transpose+split: OIH -> [t][co][ci] hi/lo -------
__global__ void prep_wt(const float* __restrict__ w0, const float* __restrict__ w1){
    int idx = blockIdx.x*blockDim.x + threadIdx.x;
    const int tot0 = 3*COUT*DD;
    const int tot1 = 5*COUT*DD;
    if (idx < tot0){
        int t = idx/(COUT*DD); int r = idx%(COUT*DD);
        int co = r/DD, ci = r%DD;
        float v = w0[(co*DD+ci)*3 + t];
        bf16 h = __float2bfloat16(v);
        g_wt0h[idx] = h;
        g_wt0l[idx] = __float2bfloat16(v - __bfloat162float(h));
    }
    if (idx < tot1){
        int t = idx/(COUT*DD); int r = idx%(COUT*DD);
        int co = r/DD, ci = r%DD;
        float v = w1[(co*DD+ci)*5 + t];
        bf16 h = __float2bfloat16(v);
        g_wt1h[idx] = h;
        g_wt1l[idx] = __float2bfloat16(v - __bfloat162float(h));
    }
}

// ---------------- tensor-core bf16x3 GEMM via wmma -----------------------------
// Y[m,n] = sum_k A[m,k]*B[n,k]  as Ah*Bh + Ah*Bl + Al*Bh (fp32 acc)
// MODE 0: g_q;  MODE 1: g_km * (1-g);  MODE 3: g_v;  MODE 2: out + bias
// MODE 4/5: conv branch 0/1, accumulate g*(conv+bias) into g_km
#define BKS 16
#define SST 24           // smem row stride in bf16 elems (16 data + 8 pad)
#define TILEE 3072       // one 128-row array: 128*SST elems
#define BUFE 12288       // 4 arrays per buffer (elems)
#define SMEM_BYTES 65536 // max(2 buffers = 49152B, epilogue 8*32*64*4 = 65536B)

// rA[0]=Ah, rA[1]=Al ; rB[0]=Bh, rB[1]=Bl  (each uint4 = 8 bf16)
template<int MODE>
__device__ __forceinline__ void g_load(int k0, int m0, int n0, int tid,
                                       uint4* rA, uint4* rB){
    const bf16* Ah = g_qh;  const bf16* Al = g_ql;
    const bf16* Bh = g_Wqh; const bf16* Bl = g_Wql;
    if (MODE==1){ Ah=g_kh;  Al=g_kl;  Bh=g_Wkh;  Bl=g_Wkl;  }
    if (MODE==2){ Ah=g_aoh; Al=g_aol; Bh=g_Woh;  Bl=g_Wol;  }
    if (MODE==3){ Ah=g_vh;  Al=g_vl;  Bh=g_Wvh;  Bl=g_Wvl;  }
    if (MODE==4){ Ah=g_kh;  Al=g_kl;  Bh=g_wt0h; Bl=g_wt0l; }
    if (MODE==5){ Ah=g_kh;  Al=g_kl;  Bh=g_wt1h; Bl=g_wt1l; }

    const int row = tid >> 1;
    const int cg  = (tid & 1)*8;

    // ---- A ----
    if (MODE<=3){
        size_t off = (size_t)(m0+row)*DD + k0 + cg;
        rA[0] = *(const uint4*)(Ah+off);
        rA[1] = *(const uint4*)(Al+off);
    } else {
        const int pad = (MODE==4)?1:2;
        int t   = k0 >> 10;           // constant within a 16-wide k tile
        int ci0 = k0 & 1023;
        int m   = m0 + row;
        int bidx = m >> 11;
        int s2  = (m & 2047) + t - pad;
        if (s2 >= 0 && s2 < SS){
            size_t off = (size_t)(bidx*SS + s2)*DD + ci0 + cg;
            rA[0] = *(const uint4*)(Ah+off);
            rA[1] = *(const uint4*)(Al+off);
        } else {
            rA[0] = make_uint4(0,0,0,0);
            rA[1] = make_uint4(0,0,0,0);
        }
    }
    // ---- B ----
    if (MODE<=3){
        size_t off = (size_t)(n0+row)*DD + k0 + cg;
        rB[0] = *(const uint4*)(Bh+off);
        rB[1] = *(const uint4*)(Bl+off);
    } else {
        int t   = k0 >> 10;
        int ci0 = k0 & 1023;
        size_t off = ((size_t)t*COUT + (n0+row))*DD + ci0 + cg;
        rB[0] = *(const uint4*)(Bh+off);
        rB[1] = *(const uint4*)(Bl+off);
    }
}

__device__ __forceinline__ void s_store(bf16* base, int tid,
                                        const uint4* rA, const uint4* rB){
    const int row = tid >> 1;
    const int cg  = (tid & 1)*8;
    bf16* p = base + row*SST + cg;
    *(uint4*)(p          ) = rA[0];
    *(uint4*)(p +   TILEE) = rA[1];
    *(uint4*)(p + 2*TILEE) = rB[0];
    *(uint4*)(p + 3*TILEE) = rB[1];
}

template<int MODE>
__global__ __launch_bounds__(256,1) void mma_gemm(
        float* __restrict__ dstp, const float* __restrict__ aux,
        const float* __restrict__ aux2){
    extern __shared__ __align__(16) bf16 smem[];
    const int tid  = threadIdx.x;
    const int wid  = tid >> 5, lane = tid & 31;
    const int wm   = wid >> 1, wn = wid & 1;     // warp grid 4x2, warp tile 32x64
    const int m0   = blockIdx.y*128;
    const int n0   = blockIdx.x*128;

    const int STEPS = (MODE==4) ? (3*DD/BKS) : (MODE==5) ? (5*DD/BKS) : (DD/BKS);

    wmma::fragment<wmma::accumulator,16,16,16,float> facc[2][4];
    #pragma unroll
    for (int i=0;i<2;i++)
        #pragma unroll
        for (int j=0;j<4;j++) wmma::fill_fragment(facc[i][j], 0.0f);

    uint4 rA[2], rB[2];

    g_load<MODE>(0, m0, n0, tid, rA, rB);
    s_store(smem, tid, rA, rB);
    g_load<MODE>(BKS, m0, n0, tid, rA, rB);
    __syncthreads();

    for (int s=0; s<STEPS; s++){
        const int buf = s & 1;
        const bf16* sAh = smem + buf*BUFE;
        const bf16* sAl = sAh + TILEE;
        const bf16* sBh = sAh + 2*TILEE;
        const bf16* sBl = sAh + 3*TILEE;

        wmma::fragment<wmma::matrix_a,16,16,16,bf16,wmma::row_major> fah[2], fal[2];
        #pragma unroll
        for (int i=0;i<2;i++){
            wmma::load_matrix_sync(fah[i], sAh + (wm*32 + i*16)*SST, SST);
            wmma::load_matrix_sync(fal[i], sAl + (wm*32 + i*16)*SST, SST);
        }
        #pragma unroll
        for (int j=0;j<4;j++){
            wmma::fragment<wmma::matrix_b,16,16,16,bf16,wmma::col_major> fbh, fbl;
            wmma::load_matrix_sync(fbh, sBh + (wn*64 + j*16)*SST, SST);
            wmma::load_matrix_sync(fbl, sBl + (wn*64 + j*16)*SST, SST);
            #pragma unroll
            for (int i=0;i<2;i++){
                wmma::mma_sync(facc[i][j], fah[i], fbh, facc[i][j]);
                wmma::mma_sync(facc[i][j], fah[i], fbl, facc[i][j]);
                wmma::mma_sync(facc[i][j], fal[i], fbh, facc[i][j]);
            }
        }
        if (s+1 < STEPS) s_store(smem + ((s+1)&1)*BUFE, tid, rA, rB);
        if (s+2 < STEPS) g_load<MODE>((s+2)*BKS, m0, n0, tid, rA, rB);
        __syncthreads();
    }

    // ---- epilogue: dump fragments to smem, then scalar writes ----
    float* ep = (float*)smem + wid*2048;   // 32x64 per warp
    #pragma unroll
    for (int i=0;i<2;i++)
        #pragma unroll
        for (int j=0;j<4;j++)
            wmma::store_matrix_sync(ep + i*16*64 + j*16, facc[i][j], 64, wmma::mem_row_major);
    __syncwarp();

    for (int t=lane; t<2048; t+=32){
        int row = t >> 6, col = t & 63;
        float val = ep[t];
        int gm = m0 + wm*32 + row;
        int gn = n0 + wn*64 + col;
        if (MODE==2){
            dstp[(size_t)gm*DD + gn] = val + aux[gn];
        }
        if (MODE==0 || MODE==1 || MODE==3){
            int bidx = gm>>11, ss2 = gm&2047;
            int h = gn>>6, d = gn&63;
            float sc = 1.0f;
            if (MODE==1) sc = 1.0f - sigm(aux[h]);
            float* dst = g_q;
            if (MODE==1) dst = g_km;
            if (MODE==3) dst = g_v;
            dst[(((size_t)bidx*HH+h)*SS+ss2)*DHD + d] = val*sc;
        }
        if (MODE==4 || MODE==5){
            const int branch = (MODE==5) ? 1 : 0;
            int bidx = gm>>11, ss2 = gm&2047;
            int gc = branch*COUT + gn;
            int h = gc>>6, d = gc&63;
            float g = sigm(aux2[h]);
            float* p = &g_km[(((size_t)bidx*HH+h)*SS+ss2)*DHD + d];
            *p = *p + g*(val + aux[gn]);
        }
    }
}

// ---------------- flash attention (64-row q tiles, online softmax) ------------
#define LDP 68
__global__ __launch_bounds__(256) void flash_attn(const int* __restrict__ mask){
    extern __shared__ float sm[];
    float (*Qs)[LDP] = (float(*)[LDP])(sm);              // [d][m]
    float (*Ks)[LDP] = (float(*)[LDP])(sm +   64*LDP);   // [d][n]
    float (*Vs)[LDP] = (float(*)[LDP])(sm + 2*64*LDP);   // [jk][d]
    float (*Ps)[LDP] = (float(*)[LDP])(sm + 3*64*LDP);   // [jk][m]

    const int bh = blockIdx.y;
    const int bidx = bh >> 4, h = bh & 15;
    const int q0 = blockIdx.x*64;
    const int tid = threadIdx.x;
    const int tx = tid & 15, ty = tid >> 4;
    const int lr = tid >> 2, lc4 = tid & 3;

    const float* Qg = g_q  + (size_t)bh*SS*DHD;
    const float* Kg = g_km + (size_t)bh*SS*DHD;
    const float* Vg = g_v  + (size_t)bh*SS*DHD;

    #pragma unroll
    for (int jj=0; jj<4; jj++){
        int c = (lc4 + jj*4)*4;
        float4 qv = *(const float4*)&Qg[(q0+lr)*DHD + c];
        Qs[c+0][lr]=qv.x; Qs[c+1][lr]=qv.y; Qs[c+2][lr]=qv.z; Qs[c+3][lr]=qv.w;
    }

    float m_run[4] = {-CUDART_INF_F,-CUDART_INF_F,-CUDART_INF_F,-CUDART_INF_F};
    float l_run[4] = {0.f,0.f,0.f,0.f};
    float o[4][4];
    #pragma unroll
    for (int i=0;i<4;i++)
        #pragma unroll
        for (int j=0;j<4;j++) o[i][j]=0.f;

    const float scl = 0.125f;
    const float NEG = -1e9f;

    for (int kb=0; kb<SS/64; kb++){
        int k0 = kb*64;
        #pragma unroll
        for (int jj=0; jj<4; jj++){
            int c = (lc4 + jj*4)*4;
            float4 kv = *(const float4*)&Kg[(k0+lr)*DHD + c];
            Ks[c+0][lr]=kv.x; Ks[c+1][lr]=kv.y; Ks[c+2][lr]=kv.z; Ks[c+3][lr]=kv.w;
            float4 vv = *(const float4*)&Vg[(k0+lr)*DHD + c];
            *(float4*)&Vs[lr][c] = vv;
        }
        __syncthreads();

        float sc[4][4];
        #pragma unroll
        for (int i=0;i<4;i++)
            #pragma unroll
            for (int j=0;j<4;j++) sc[i][j]=0.f;

        #pragma unroll 16
        for (int kt=0; kt<64; kt++){
            float4 aq = *(const float4*)&Qs[kt][ty*4];
            float4 bk = *(const float4*)&Ks[kt][tx*4];
            float ar[4]={aq.x,aq.y,aq.z,aq.w};
            float br[4]={bk.x,bk.y,bk.z,bk.w};
            #pragma unroll
            for (int i=0;i<4;i++)
                #pragma unroll
                for (int j=0;j<4;j++) sc[i][j] = fmaf(ar[i], br[j], sc[i][j]);
        }

        #pragma unroll
        for (int i=0;i<4;i++){
            const int4 mr = *(const int4*)&mask[((size_t)bidx*SS + q0+ty*4+i)*SS + k0 + tx*4];
            sc[i][0] = mr.x ? sc[i][0]*scl : NEG;
            sc[i][1] = mr.y ? sc[i][1]*scl : NEG;
            sc[i][2] = mr.z ? sc[i][2]*scl : NEG;
            sc[i][3] = mr.w ? sc[i][3]*scl : NEG;
        }

        #pragma unroll
        for (int i=0;i<4;i++){
            float rm = fmaxf(fmaxf(sc[i][0],sc[i][1]), fmaxf(sc[i][2],sc[i][3]));
            #pragma unroll
            for (int off=8; off>=1; off>>=1)
                rm = fmaxf(rm, __shfl_xor_sync(0xffffffffu, rm, off));
            float mnew = fmaxf(m_run[i], rm);
            float corr = __expf(m_run[i] - mnew);
            float ps = 0.f;
            #pragma unroll
            for (int j=0;j<4;j++){
                float p = __expf(sc[i][j] - mnew);
                Ps[tx*4+j][ty*4+i] = p;
                ps += p;
            }
            #pragma unroll
            for (int off=8; off>=1; off>>=1)
                ps += __shfl_xor_sync(0xffffffffu, ps, off);
            l_run[i] = l_run[i]*corr + ps;
            m_run[i] = mnew;
            o[i][0]*=corr; o[i][1]*=corr; o[i][2]*=corr; o[i][3]*=corr;
        }
        __syncthreads();

        #pragma unroll 16
        for (int jk=0; jk<64; jk++){
            float4 pp = *(const float4*)&Ps[jk][ty*4];
            float4 vv = *(const float4*)&Vs[jk][tx*4];
            float pr[4]={pp.x,pp.y,pp.z,pp.w};
            float vr[4]={vv.x,vv.y,vv.z,vv.w};
            #pragma unroll
            for (int i=0;i<4;i++)
                #pragma unroll
                for (int j=0;j<4;j++) o[i][j] = fmaf(pr[i], vr[j], o[i][j]);
        }
        __syncthreads();
    }

    #pragma unroll
    for (int i=0;i<4;i++){
        float inv = 1.0f / l_run[i];
        int srow = q0 + ty*4 + i;
        float4 v;
        v.x=o[i][0]*inv; v.y=o[i][1]*inv; v.z=o[i][2]*inv; v.w=o[i][3]*inv;
        *(float4*)&g_ao[((size_t)bidx*SS + srow)*DD + h*DHD + tx*4] = v;
    }
}

// ---------------- launch ------------------------------------------------------
extern "C" void kernel_launch(void* const* d_in, const int* in_sizes, int n_in,
                              void* d_out, int out_size){
    const float* q    = (const float*)d_in[0];
    const float* k    = (const float*)d_in[1];
    const float* v    = (const float*)d_in[2];
    const int*   mask = (const int*)  d_in[3];
    const float* Wq   = (const float*)d_in[4];
    const float* Wk   = (const float*)d_in[5];
    const float* Wv   = (const float*)d_in[6];
    const float* Wo   = (const float*)d_in[7];
    const float* bo   = (const float*)d_in[8];
    const float* cw0  = (const float*)d_in[9];
    const float* cb0  = (const float*)d_in[10];
    const float* cw1  = (const float*)d_in[11];
    const float* cb1  = (const float*)d_in[12];
    const float* gate = (const float*)d_in[13];
    float* out = (float*)d_out;

    const int nBig4 = MTOT*DD/4;   // 1M float4
    const int nW4   = DD*DD/4;     // 256K float4

    cvt_hilo<0><<<(nBig4+255)/256,256>>>(q, nBig4);
    cvt_hilo<1><<<(nBig4+255)/256,256>>>(k, nBig4);
    cvt_hilo<2><<<(nBig4+255)/256,256>>>(v, nBig4);
    cvt_hilo<3><<<(nW4+255)/256,256>>>(Wq, nW4);
    cvt_hilo<4><<<(nW4+255)/256,256>>>(Wk, nW4);
    cvt_hilo<5><<<(nW4+255)/256,256>>>(Wv, nW4);
    cvt_hilo<6><<<(nW4+255)/256,256>>>(Wo, nW4);
    prep_wt<<<(5*COUT*DD+255)/256,256>>>(cw0, cw1);

    cudaFuncSetAttribute(mma_gemm<0>, cudaFuncAttributeMaxDynamicSharedMemorySize, SMEM_BYTES);
    cudaFuncSetAttribute(mma_gemm<1>, cudaFuncAttributeMaxDynamicSharedMemorySize, SMEM_BYTES);
    cudaFuncSetAttribute(mma_gemm<2>, cudaFuncAttributeMaxDynamicSharedMemorySize, SMEM_BYTES);
    cudaFuncSetAttribute(mma_gemm<3>, cudaFuncAttributeMaxDynamicSharedMemorySize, SMEM_BYTES);
    cudaFuncSetAttribute(mma_gemm<4>, cudaFuncAttributeMaxDynamicSharedMemorySize, SMEM_BYTES);
    cudaFuncSetAttribute(mma_gemm<5>, cudaFuncAttributeMaxDynamicSharedMemorySize, SMEM_BYTES);

    dim3 gproj(DD/128, MTOT/128);   // (8, 32)
    dim3 gconv(COUT/128, MTOT/128); // (4, 32)

    mma_gemm<0><<<gproj,256,SMEM_BYTES>>>(nullptr, nullptr, nullptr);
    mma_gemm<1><<<gproj,256,SMEM_BYTES>>>(nullptr, gate, nullptr);
    mma_gemm<3><<<gproj,256,SMEM_BYTES>>>(nullptr, nullptr, nullptr);
    mma_gemm<4><<<gconv,256,SMEM_BYTES>>>(nullptr, cb0, gate);
    mma_gemm<5><<<gconv,256,SMEM_BYTES>>>(nullptr, cb1, gate);

    int smem = 4*64*LDP*sizeof(float);
    cudaFuncSetAttribute(flash_attn, cudaFuncAttributeMaxDynamicSharedMemorySize, smem);
    flash_attn<<<dim3(SS/64, BB*HH), 256, smem>>>(mask);

    cvt_hilo<7><<<(nBig4+255)/256,256>>>(nullptr, nBig4);
    mma_gemm<2><<<gproj,256,SMEM_BYTES>>>(out, bo, nullptr);
}